// round 11
// baseline (speedup 1.0000x reference)
#include <cuda_runtime.h>
#include <cuda_bf16.h>
#include <cstdint>

#define BATCH 4
#define SEQ   4096
#define EMB   1024
#define ROWS  (BATCH * SEQ)      // 16384
#define SCALE 0.03125f           // 1/sqrt(1024)

// GEMM tiling: CTA 128x256, warp tile 32x64 (4x4 warps), 512 threads
#define CTM 128
#define CTN 256
#define KSTAGE 32
#define NSTAGES 3
#define KSTEPS (EMB / KSTAGE)    // 32
#define NTHREADS 512

#define ROWSTRIDE_B 80                        // bytes (32 bf16 + 16B pad)
#define A_MAT (128 * ROWSTRIDE_B)             // 10240
#define B_MAT (256 * ROWSTRIDE_B)             // 20480
#define O_AHI 0
#define O_ALO A_MAT
#define O_BHI (2 * A_MAT)
#define O_BLO (2 * A_MAT + B_MAT)
#define STAGE_BYTES (2 * A_MAT + 2 * B_MAT)   // 61440
#define DSMEM_BYTES (NSTAGES * STAGE_BYTES)   // 184320

// ---------------------------------------------------------------------------
// Scratch (device globals)
// ---------------------------------------------------------------------------
__device__ __nv_bfloat16 g_Xhi[(size_t)ROWS * EMB];
__device__ __nv_bfloat16 g_Xlo[(size_t)ROWS * EMB];
__device__ __nv_bfloat16 g_Wq_hi[EMB * EMB], g_Wq_lo[EMB * EMB];
__device__ __nv_bfloat16 g_Wk_hi[EMB * EMB], g_Wk_lo[EMB * EMB];
__device__ __nv_bfloat16 g_Mt_hi[EMB * EMB], g_Mt_lo[EMB * EMB];   // (Wk Wq^T)/32
__device__ __nv_bfloat16 g_Yhi[(size_t)ROWS * EMB], g_Ylo[(size_t)ROWS * EMB];
__device__ float g_L[(size_t)BATCH * SEQ * SEQ];   // 256 MB
__device__ float g_vmean[ROWS];
__device__ float g_wvbar[EMB];
__device__ unsigned int g_rowmax[ROWS];

// ---------------------------------------------------------------------------
// Helpers
// ---------------------------------------------------------------------------
__device__ __forceinline__ uint32_t smem_u32(const void* p) {
    uint32_t a;
    asm("{ .reg .u64 t; cvta.to.shared.u64 t, %1; cvt.u32.u64 %0, t; }" : "=r"(a) : "l"(p));
    return a;
}
__device__ __forceinline__ void cp_async16(uint32_t dst, const void* src) {
    asm volatile("cp.async.cg.shared.global [%0], [%1], 16;" :: "r"(dst), "l"(src) : "memory");
}
__device__ __forceinline__ void cp_commit() {
    asm volatile("cp.async.commit_group;" ::: "memory");
}
template <int NN>
__device__ __forceinline__ void cp_wait() {
    asm volatile("cp.async.wait_group %0;" :: "n"(NN) : "memory");
}
__device__ __forceinline__ void ldm_x4(uint32_t* r, uint32_t addr) {
    asm volatile("ldmatrix.sync.aligned.m8n8.x4.shared.b16 {%0,%1,%2,%3}, [%4];"
                 : "=r"(r[0]), "=r"(r[1]), "=r"(r[2]), "=r"(r[3]) : "r"(addr));
}
__device__ __forceinline__ void mma16816(float* c, const uint32_t* a, uint32_t b0, uint32_t b1) {
    asm volatile("mma.sync.aligned.m16n8k16.row.col.f32.bf16.bf16.f32 "
                 "{%0,%1,%2,%3}, {%4,%5,%6,%7}, {%8,%9}, {%0,%1,%2,%3};"
                 : "+f"(c[0]), "+f"(c[1]), "+f"(c[2]), "+f"(c[3])
                 : "r"(a[0]), "r"(a[1]), "r"(a[2]), "r"(a[3]), "r"(b0), "r"(b1));
}
__device__ __forceinline__ uint32_t packbf(__nv_bfloat16 a, __nv_bfloat16 b) {
    __nv_bfloat162 t = __halves2bfloat162(a, b);
    return *reinterpret_cast<uint32_t*>(&t);
}
__device__ __forceinline__ unsigned int fenc(float f) {
    unsigned int b = __float_as_uint(f);
    return (b & 0x80000000u) ? ~b : (b | 0x80000000u);
}
__device__ __forceinline__ float fdec(unsigned int u) {
    unsigned int b = (u & 0x80000000u) ? (u & 0x7FFFFFFFu) : ~u;
    return __uint_as_float(b);
}

// ---------------------------------------------------------------------------
// prep1: range-branched mega-kernel
// ---------------------------------------------------------------------------
#define P_SPLIT_END 16384
#define P_WQ_END    17408
#define P_WK_END    18432
#define P_WV_END    18560
#define P_RM_END    18624

__device__ __forceinline__ void split4(const float4* __restrict__ src,
                                       uint2* __restrict__ hi, uint2* __restrict__ lo, int i) {
    float4 v = src[i];
    __nv_bfloat16 h0 = __float2bfloat16(v.x), h1 = __float2bfloat16(v.y);
    __nv_bfloat16 h2 = __float2bfloat16(v.z), h3 = __float2bfloat16(v.w);
    __nv_bfloat16 l0 = __float2bfloat16(v.x - __bfloat162float(h0));
    __nv_bfloat16 l1 = __float2bfloat16(v.y - __bfloat162float(h1));
    __nv_bfloat16 l2 = __float2bfloat16(v.z - __bfloat162float(h2));
    __nv_bfloat16 l3 = __float2bfloat16(v.w - __bfloat162float(h3));
    hi[i] = make_uint2(packbf(h0, h1), packbf(h2, h3));
    lo[i] = make_uint2(packbf(l0, l1), packbf(l2, l3));
}

__global__ __launch_bounds__(256)
void prep1_kernel(const float* __restrict__ X,
                  const float* __restrict__ Wq,
                  const float* __restrict__ Wk,
                  const float* __restrict__ Wv) {
    const int b = blockIdx.x;
    if (b < P_SPLIT_END) {
        split4((const float4*)X, (uint2*)g_Xhi, (uint2*)g_Xlo, b * 256 + threadIdx.x);
    } else if (b < P_WQ_END) {
        split4((const float4*)Wq, (uint2*)g_Wq_hi, (uint2*)g_Wq_lo,
               (b - P_SPLIT_END) * 256 + threadIdx.x);
    } else if (b < P_WK_END) {
        split4((const float4*)Wk, (uint2*)g_Wk_hi, (uint2*)g_Wk_lo,
               (b - P_WQ_END) * 256 + threadIdx.x);
    } else if (b < P_WV_END) {
        int row = (b - P_WK_END) * 8 + (threadIdx.x >> 5);
        int lane = threadIdx.x & 31;
        const float* p = Wv + (size_t)row * EMB;
        float s = 0.f;
        #pragma unroll 4
        for (int j = lane; j < EMB; j += 32) s += p[j];
        #pragma unroll
        for (int o = 16; o > 0; o >>= 1) s += __shfl_xor_sync(0xffffffffu, s, o);
        if (lane == 0) g_wvbar[row] = s * (1.0f / (float)EMB);
    } else {
        int i = (b - P_WV_END) * 256 + threadIdx.x;
        g_rowmax[i] = 0u;
    }
}

__global__ void vmean_kernel(const float* __restrict__ X) {
    int row = blockIdx.x * (blockDim.x >> 5) + (threadIdx.x >> 5);
    int lane = threadIdx.x & 31;
    if (row >= ROWS) return;
    const float4* p = (const float4*)(X + (size_t)row * EMB);
    const float4* w = (const float4*)g_wvbar;
    float s = 0.f;
    #pragma unroll 8
    for (int j = lane; j < EMB / 4; j += 32) {
        float4 a = p[j], b = w[j];
        s += a.x * b.x + a.y * b.y + a.z * b.z + a.w * b.w;
    }
    #pragma unroll
    for (int o = 16; o > 0; o >>= 1) s += __shfl_xor_sync(0xffffffffu, s, o);
    if (lane == 0) g_vmean[row] = s;
}

// ---------------------------------------------------------------------------
// bf16x2-split NT GEMM: CTA 128x256, warp tile 32x64, 3-stage cp.async
// C[M,N] = scale * A[M,K] . B[N,K]^T
// mode 0: write C as split bf16 (scaled); mode 1: write fp32 (scaled) + rowmax
// ---------------------------------------------------------------------------
__global__ __launch_bounds__(NTHREADS, 1)
void gemm_nt_mma(const __nv_bfloat16* __restrict__ Ahi, const __nv_bfloat16* __restrict__ Alo,
                 const __nv_bfloat16* __restrict__ Bhi, const __nv_bfloat16* __restrict__ Blo,
                 size_t aBatch, size_t bBatch, int mode,
                 float* __restrict__ Cf, size_t cBatch, int ldC, float scale,
                 __nv_bfloat16* __restrict__ Chi, __nv_bfloat16* __restrict__ Clo) {
    extern __shared__ char smem[];
    const uint32_t sbase = smem_u32(smem);
    const int tid = threadIdx.x;
    const int lane = tid & 31;
    const int wid = tid >> 5;
    const int wm = wid >> 2;          // 0..3 -> M
    const int wn = wid & 3;           // 0..3 -> N (64 each)
    const int bz = blockIdx.z;
    const int mBase = blockIdx.y * CTM;
    const int nBase = blockIdx.x * CTN;

    const __nv_bfloat16* gAhi = Ahi + (size_t)bz * aBatch + (size_t)mBase * EMB;
    const __nv_bfloat16* gAlo = Alo + (size_t)bz * aBatch + (size_t)mBase * EMB;
    const __nv_bfloat16* gBhi = Bhi + (size_t)bz * bBatch + (size_t)nBase * EMB;
    const __nv_bfloat16* gBlo = Blo + (size_t)bz * bBatch + (size_t)nBase * EMB;

    const int rA = tid >> 2, sA = tid & 3;          // A: 512 chunks (128 rows x 4)
    const int rB0 = tid >> 2, rB1 = 128 + (tid >> 2);

    const uint32_t aRowOff = (uint32_t)(wm * 32 + (lane & 15)) * ROWSTRIDE_B;
    const uint32_t aKsel = ((lane >> 4) & 1) * 16;
    const uint32_t bRowOff = (uint32_t)(wn * 64 + ((lane >> 4) & 1) * 8 + (lane & 7)) * ROWSTRIDE_B;
    const uint32_t bKsel = ((lane >> 3) & 1) * 16;

    float acc[2][8][4];
    #pragma unroll
    for (int i = 0; i < 2; i++)
        #pragma unroll
        for (int j = 0; j < 8; j++)
            #pragma unroll
            for (int q = 0; q < 4; q++) acc[i][j][q] = 0.f;

    auto load_stage = [&](int k0, int buf) {
        uint32_t sb = sbase + buf * STAGE_BYTES;
        const size_t kOff = (size_t)k0 * KSTAGE;
        cp_async16(sb + O_AHI + rA * ROWSTRIDE_B + sA * 16, gAhi + (size_t)rA * EMB + kOff + sA * 8);
        cp_async16(sb + O_ALO + rA * ROWSTRIDE_B + sA * 16, gAlo + (size_t)rA * EMB + kOff + sA * 8);
        cp_async16(sb + O_BHI + rB0 * ROWSTRIDE_B + sA * 16, gBhi + (size_t)rB0 * EMB + kOff + sA * 8);
        cp_async16(sb + O_BHI + rB1 * ROWSTRIDE_B + sA * 16, gBhi + (size_t)rB1 * EMB + kOff + sA * 8);
        cp_async16(sb + O_BLO + rB0 * ROWSTRIDE_B + sA * 16, gBlo + (size_t)rB0 * EMB + kOff + sA * 8);
        cp_async16(sb + O_BLO + rB1 * ROWSTRIDE_B + sA * 16, gBlo + (size_t)rB1 * EMB + kOff + sA * 8);
    };

    #pragma unroll
    for (int s = 0; s < NSTAGES - 1; s++) {
        load_stage(s, s);
        cp_commit();
    }

    for (int k0 = 0; k0 < KSTEPS; k0++) {
        cp_wait<NSTAGES - 2>();
        __syncthreads();
        if (k0 + NSTAGES - 1 < KSTEPS)
            load_stage(k0 + NSTAGES - 1, (k0 + NSTAGES - 1) % NSTAGES);
        cp_commit();

        const uint32_t sb = sbase + (k0 % NSTAGES) * STAGE_BYTES;
        #pragma unroll
        for (int kk = 0; kk < 2; kk++) {
            const uint32_t kByte = kk * 32;
            uint32_t ah[2][4], al[2][4], b[16];
            #pragma unroll
            for (int mt = 0; mt < 2; mt++) {
                uint32_t ao = aRowOff + (uint32_t)(mt * 16) * ROWSTRIDE_B + kByte + aKsel;
                ldm_x4(ah[mt], sb + O_AHI + ao);
                ldm_x4(al[mt], sb + O_ALO + ao);
            }
            // B-hi into b[], run hh and lh passes
            #pragma unroll
            for (int p = 0; p < 4; p++) {
                uint32_t bo = bRowOff + (uint32_t)(p * 16) * ROWSTRIDE_B + kByte + bKsel;
                ldm_x4(&b[p * 4], sb + O_BHI + bo);
            }
            #pragma unroll
            for (int mt = 0; mt < 2; mt++)
                #pragma unroll
                for (int nt = 0; nt < 8; nt++)
                    mma16816(acc[mt][nt], ah[mt], b[nt * 2], b[nt * 2 + 1]);
            #pragma unroll
            for (int mt = 0; mt < 2; mt++)
                #pragma unroll
                for (int nt = 0; nt < 8; nt++)
                    mma16816(acc[mt][nt], al[mt], b[nt * 2], b[nt * 2 + 1]);
            // B-lo overwrites b[], run hl pass
            #pragma unroll
            for (int p = 0; p < 4; p++) {
                uint32_t bo = bRowOff + (uint32_t)(p * 16) * ROWSTRIDE_B + kByte + bKsel;
                ldm_x4(&b[p * 4], sb + O_BLO + bo);
            }
            #pragma unroll
            for (int mt = 0; mt < 2; mt++)
                #pragma unroll
                for (int nt = 0; nt < 8; nt++)
                    mma16816(acc[mt][nt], ah[mt], b[nt * 2], b[nt * 2 + 1]);
        }
    }
    cp_wait<0>();

    const int mrow = mBase + wm * 32 + (lane >> 2);
    const int ncol = nBase + wn * 64 + (lane & 3) * 2;
    if (mode == 0) {
        #pragma unroll
        for (int mt = 0; mt < 2; mt++)
            #pragma unroll
            for (int nt = 0; nt < 8; nt++) {
                #pragma unroll
                for (int half = 0; half < 2; half++) {
                    float v0 = acc[mt][nt][half * 2 + 0] * scale;
                    float v1 = acc[mt][nt][half * 2 + 1] * scale;
                    __nv_bfloat16 h0 = __float2bfloat16(v0);
                    __nv_bfloat16 h1 = __float2bfloat16(v1);
                    __nv_bfloat16 l0 = __float2bfloat16(v0 - __bfloat162float(h0));
                    __nv_bfloat16 l1 = __float2bfloat16(v1 - __bfloat162float(h1));
                    size_t o = (size_t)(mrow + mt * 16 + half * 8) * EMB + (ncol + nt * 8);
                    *(uint32_t*)(Chi + o) = packbf(h0, h1);
                    *(uint32_t*)(Clo + o) = packbf(l0, l1);
                }
            }
    } else {
        float* Cp = Cf + (size_t)bz * cBatch;
        #pragma unroll
        for (int mt = 0; mt < 2; mt++) {
            #pragma unroll
            for (int half = 0; half < 2; half++) {
                float rmax = -3.4e38f;
                #pragma unroll
                for (int nt = 0; nt < 8; nt++) {
                    float2 v;
                    v.x = acc[mt][nt][half * 2 + 0] * scale;
                    v.y = acc[mt][nt][half * 2 + 1] * scale;
                    rmax = fmaxf(rmax, fmaxf(v.x, v.y));
                    *(float2*)(Cp + (size_t)(mrow + mt * 16 + half * 8) * ldC + (ncol + nt * 8)) = v;
                }
                rmax = fmaxf(rmax, __shfl_xor_sync(0xffffffffu, rmax, 1));
                rmax = fmaxf(rmax, __shfl_xor_sync(0xffffffffu, rmax, 2));
                if ((lane & 3) == 0) {
                    int grow = bz * SEQ + mrow + mt * 16 + half * 8;
                    atomicMax(&g_rowmax[grow], fenc(rmax));
                }
            }
        }
    }
}

// ---------------------------------------------------------------------------
// Single-pass softmax-weighted mean (vectorized), uses precomputed row max
// ---------------------------------------------------------------------------
__global__ __launch_bounds__(256)
void softmax_out_kernel(float* __restrict__ out) {
    const int r = blockIdx.x;
    const float4* row = (const float4*)(g_L + (size_t)r * SEQ);
    const float4* vm = (const float4*)(g_vmean + (r >> 12) * SEQ);
    const int tid = threadIdx.x;
    const float m = fdec(g_rowmax[r]);

    __shared__ float red0[256];
    __shared__ float red1[256];

    float s0 = 0.f, s1 = 0.f;
    #pragma unroll
    for (int j = tid; j < SEQ / 4; j += 256) {
        float4 l = row[j];
        float4 w = vm[j];
        float e0 = __expf(l.x - m), e1 = __expf(l.y - m);
        float e2 = __expf(l.z - m), e3 = __expf(l.w - m);
        s0 += (e0 + e1) + (e2 + e3);
        s1 += e0 * w.x + e1 * w.y + e2 * w.z + e3 * w.w;
    }
    red0[tid] = s0;
    red1[tid] = s1;
    __syncthreads();
    for (int s = 128; s > 0; s >>= 1) {
        if (tid < s) { red0[tid] += red0[tid + s]; red1[tid] += red1[tid + s]; }
        __syncthreads();
    }
    if (tid == 0) out[r] = red1[0] / red0[0];
}

// ---------------------------------------------------------------------------
extern "C" void kernel_launch(void* const* d_in, const int* in_sizes, int n_in,
                              void* d_out, int out_size) {
    const float* X  = (const float*)d_in[0];
    const float* Wq = (const float*)d_in[1];
    const float* Wk = (const float*)d_in[2];
    const float* Wv = (const float*)d_in[3];
    float* out = (float*)d_out;

    __nv_bfloat16 *Xhi, *Xlo, *Wqh, *Wql, *Wkh, *Wkl, *Mth, *Mtl, *Yh, *Yl;
    float *Lp;
    cudaGetSymbolAddress((void**)&Xhi, g_Xhi);
    cudaGetSymbolAddress((void**)&Xlo, g_Xlo);
    cudaGetSymbolAddress((void**)&Wqh, g_Wq_hi);
    cudaGetSymbolAddress((void**)&Wql, g_Wq_lo);
    cudaGetSymbolAddress((void**)&Wkh, g_Wk_hi);
    cudaGetSymbolAddress((void**)&Wkl, g_Wk_lo);
    cudaGetSymbolAddress((void**)&Mth, g_Mt_hi);
    cudaGetSymbolAddress((void**)&Mtl, g_Mt_lo);
    cudaGetSymbolAddress((void**)&Yh, g_Yhi);
    cudaGetSymbolAddress((void**)&Yl, g_Ylo);
    cudaGetSymbolAddress((void**)&Lp, g_L);

    cudaFuncSetAttribute(gemm_nt_mma, cudaFuncAttributeMaxDynamicSharedMemorySize, DSMEM_BYTES);

    // 1. prep
    prep1_kernel<<<P_RM_END, 256>>>(X, Wq, Wk, Wv);
    // 2. vmean
    vmean_kernel<<<ROWS / 8, 256>>>(X);

    // 3. Mt = (Wk . Wq^T) / 32  -> split bf16   [1024 x 1024]
    {
        dim3 grid(EMB / CTN, EMB / CTM, 1);
        gemm_nt_mma<<<grid, NTHREADS, DSMEM_BYTES>>>(Wkh, Wkl, Wqh, Wql, 0, 0,
                                                     0, nullptr, 0, 0, SCALE, Mth, Mtl);
    }

    // 4. Y = X . Mt^T -> split bf16   [16384 x 1024]
    {
        dim3 grid(EMB / CTN, ROWS / CTM, 1);
        gemm_nt_mma<<<grid, NTHREADS, DSMEM_BYTES>>>(Xhi, Xlo, Mth, Mtl, 0, 0,
                                                     0, nullptr, 0, 0, 1.0f, Yh, Yl);
    }

    // 5. logits = Y . X^T (batched) + fused row-max
    {
        dim3 grid(SEQ / CTN, SEQ / CTM, BATCH);
        gemm_nt_mma<<<grid, NTHREADS, DSMEM_BYTES>>>(Yh, Yl, Xhi, Xlo,
                                                     (size_t)SEQ * EMB, (size_t)SEQ * EMB,
                                                     1, Lp, (size_t)SEQ * SEQ, SEQ, 1.0f,
                                                     nullptr, nullptr);
    }

    // 6. single-pass softmax-weighted mean
    softmax_out_kernel<<<ROWS, 256>>>(out);
}

// round 12
// speedup vs baseline: 1.0001x; 1.0001x over previous
#include <cuda_runtime.h>
#include <cuda_bf16.h>
#include <cstdint>

#define BATCH 4
#define SEQ   4096
#define EMB   1024
#define ROWS  (BATCH * SEQ)      // 16384
#define SCALE 0.03125f           // 1/sqrt(1024)

// GEMM tiling (R8 config): CTA 128x128, warp tile 32x32, 512 threads, 4 stages
#define CTM 128
#define CTN 128
#define KSTAGE 32
#define NSTAGES 4
#define KSTEPS (EMB / KSTAGE)    // 32
#define NTHREADS 512

#define ROWSTRIDE_B 80           // bytes (32 bf16 + pad)
#define MAT_BYTES  (128 * ROWSTRIDE_B)       // 10240
#define STAGE_BYTES (4 * MAT_BYTES)          // 40960
#define DSMEM_BYTES (NSTAGES * STAGE_BYTES)  // 163840

// ---------------------------------------------------------------------------
// Scratch (device globals)
// ---------------------------------------------------------------------------
__device__ __nv_bfloat16 g_Xhi[(size_t)ROWS * EMB];
__device__ __nv_bfloat16 g_Xlo[(size_t)ROWS * EMB];
__device__ __nv_bfloat16 g_Wq_hi[EMB * EMB], g_Wq_lo[EMB * EMB];
__device__ __nv_bfloat16 g_Wk_hi[EMB * EMB], g_Wk_lo[EMB * EMB];
__device__ __nv_bfloat16 g_Mt_hi[EMB * EMB], g_Mt_lo[EMB * EMB];   // (Wk Wq^T)/32
__device__ __nv_bfloat16 g_Yhi[(size_t)ROWS * EMB], g_Ylo[(size_t)ROWS * EMB];
__device__ float g_L[(size_t)BATCH * SEQ * SEQ];   // 256 MB
__device__ float g_vmean[ROWS];
__device__ float g_wvbar[EMB];
__device__ unsigned int g_rowmax[ROWS];

// ---------------------------------------------------------------------------
// Helpers
// ---------------------------------------------------------------------------
__device__ __forceinline__ uint32_t smem_u32(const void* p) {
    uint32_t a;
    asm("{ .reg .u64 t; cvta.to.shared.u64 t, %1; cvt.u32.u64 %0, t; }" : "=r"(a) : "l"(p));
    return a;
}
__device__ __forceinline__ void cp_async16(uint32_t dst, const void* src) {
    asm volatile("cp.async.cg.shared.global [%0], [%1], 16;" :: "r"(dst), "l"(src) : "memory");
}
__device__ __forceinline__ void cp_commit() {
    asm volatile("cp.async.commit_group;" ::: "memory");
}
template <int NN>
__device__ __forceinline__ void cp_wait() {
    asm volatile("cp.async.wait_group %0;" :: "n"(NN) : "memory");
}
__device__ __forceinline__ void ldm_x4(uint32_t* r, uint32_t addr) {
    asm volatile("ldmatrix.sync.aligned.m8n8.x4.shared.b16 {%0,%1,%2,%3}, [%4];"
                 : "=r"(r[0]), "=r"(r[1]), "=r"(r[2]), "=r"(r[3]) : "r"(addr));
}
__device__ __forceinline__ void mma16816(float* c, const uint32_t* a, uint32_t b0, uint32_t b1) {
    asm volatile("mma.sync.aligned.m16n8k16.row.col.f32.bf16.bf16.f32 "
                 "{%0,%1,%2,%3}, {%4,%5,%6,%7}, {%8,%9}, {%0,%1,%2,%3};"
                 : "+f"(c[0]), "+f"(c[1]), "+f"(c[2]), "+f"(c[3])
                 : "r"(a[0]), "r"(a[1]), "r"(a[2]), "r"(a[3]), "r"(b0), "r"(b1));
}
__device__ __forceinline__ uint32_t packbf(__nv_bfloat16 a, __nv_bfloat16 b) {
    __nv_bfloat162 t = __halves2bfloat162(a, b);
    return *reinterpret_cast<uint32_t*>(&t);
}
__device__ __forceinline__ unsigned int fenc(float f) {
    unsigned int b = __float_as_uint(f);
    return (b & 0x80000000u) ? ~b : (b | 0x80000000u);
}
__device__ __forceinline__ float fdec(unsigned int u) {
    unsigned int b = (u & 0x80000000u) ? (u & 0x7FFFFFFFu) : ~u;
    return __uint_as_float(b);
}

// ---------------------------------------------------------------------------
// prep1: range-branched mega-kernel
// ---------------------------------------------------------------------------
#define P_SPLIT_END 16384
#define P_WQ_END    17408
#define P_WK_END    18432
#define P_WV_END    18560
#define P_RM_END    18624

__device__ __forceinline__ void split4(const float4* __restrict__ src,
                                       uint2* __restrict__ hi, uint2* __restrict__ lo, int i) {
    float4 v = src[i];
    __nv_bfloat16 h0 = __float2bfloat16(v.x), h1 = __float2bfloat16(v.y);
    __nv_bfloat16 h2 = __float2bfloat16(v.z), h3 = __float2bfloat16(v.w);
    __nv_bfloat16 l0 = __float2bfloat16(v.x - __bfloat162float(h0));
    __nv_bfloat16 l1 = __float2bfloat16(v.y - __bfloat162float(h1));
    __nv_bfloat16 l2 = __float2bfloat16(v.z - __bfloat162float(h2));
    __nv_bfloat16 l3 = __float2bfloat16(v.w - __bfloat162float(h3));
    hi[i] = make_uint2(packbf(h0, h1), packbf(h2, h3));
    lo[i] = make_uint2(packbf(l0, l1), packbf(l2, l3));
}

__global__ __launch_bounds__(256)
void prep1_kernel(const float* __restrict__ X,
                  const float* __restrict__ Wq,
                  const float* __restrict__ Wk,
                  const float* __restrict__ Wv) {
    const int b = blockIdx.x;
    if (b < P_SPLIT_END) {
        split4((const float4*)X, (uint2*)g_Xhi, (uint2*)g_Xlo, b * 256 + threadIdx.x);
    } else if (b < P_WQ_END) {
        split4((const float4*)Wq, (uint2*)g_Wq_hi, (uint2*)g_Wq_lo,
               (b - P_SPLIT_END) * 256 + threadIdx.x);
    } else if (b < P_WK_END) {
        split4((const float4*)Wk, (uint2*)g_Wk_hi, (uint2*)g_Wk_lo,
               (b - P_WQ_END) * 256 + threadIdx.x);
    } else if (b < P_WV_END) {
        int row = (b - P_WK_END) * 8 + (threadIdx.x >> 5);
        int lane = threadIdx.x & 31;
        const float* p = Wv + (size_t)row * EMB;
        float s = 0.f;
        #pragma unroll 4
        for (int j = lane; j < EMB; j += 32) s += p[j];
        #pragma unroll
        for (int o = 16; o > 0; o >>= 1) s += __shfl_xor_sync(0xffffffffu, s, o);
        if (lane == 0) g_wvbar[row] = s * (1.0f / (float)EMB);
    } else {
        int i = (b - P_WV_END) * 256 + threadIdx.x;
        g_rowmax[i] = 0u;
    }
}

__global__ void vmean_kernel(const float* __restrict__ X) {
    int row = blockIdx.x * (blockDim.x >> 5) + (threadIdx.x >> 5);
    int lane = threadIdx.x & 31;
    if (row >= ROWS) return;
    const float4* p = (const float4*)(X + (size_t)row * EMB);
    const float4* w = (const float4*)g_wvbar;
    float s = 0.f;
    #pragma unroll 8
    for (int j = lane; j < EMB / 4; j += 32) {
        float4 a = p[j], b = w[j];
        s += a.x * b.x + a.y * b.y + a.z * b.z + a.w * b.w;
    }
    #pragma unroll
    for (int o = 16; o > 0; o >>= 1) s += __shfl_xor_sync(0xffffffffu, s, o);
    if (lane == 0) g_vmean[row] = s;
}

// ---------------------------------------------------------------------------
// bf16x2-split NT GEMM, 512 threads, 4x4 warps, warp tile 32x32.
// Fine-grained pipelining: every ldmatrix group is issued under the shadow of
// the previous 8-HMMA pass (al only needed for lh, bl only for hl).
// ---------------------------------------------------------------------------
__global__ __launch_bounds__(NTHREADS)
void gemm_nt_mma(const __nv_bfloat16* __restrict__ Ahi, const __nv_bfloat16* __restrict__ Alo,
                 const __nv_bfloat16* __restrict__ Bhi, const __nv_bfloat16* __restrict__ Blo,
                 size_t aBatch, size_t bBatch, int mode,
                 float* __restrict__ Cf, size_t cBatch, int ldC, float scale,
                 __nv_bfloat16* __restrict__ Chi, __nv_bfloat16* __restrict__ Clo) {
    extern __shared__ char smem[];
    const uint32_t sbase = smem_u32(smem);
    const int tid = threadIdx.x;
    const int lane = tid & 31;
    const int wid = tid >> 5;
    const int wm = wid >> 2;          // 0..3
    const int wn = wid & 3;           // 0..3
    const int bz = blockIdx.z;
    const int mBase = blockIdx.y * CTM;
    const int nBase = blockIdx.x * CTN;

    const __nv_bfloat16* gsrc[4];
    gsrc[0] = Ahi + (size_t)bz * aBatch + (size_t)mBase * EMB;
    gsrc[1] = Alo + (size_t)bz * aBatch + (size_t)mBase * EMB;
    gsrc[2] = Bhi + (size_t)bz * bBatch + (size_t)nBase * EMB;
    gsrc[3] = Blo + (size_t)bz * bBatch + (size_t)nBase * EMB;

    const int r0 = tid >> 2, s0 = tid & 3;

    const uint32_t aRowOff = (uint32_t)(wm * 32 + (lane & 15)) * ROWSTRIDE_B;
    const uint32_t aKsel = ((lane >> 4) & 1) * 16;
    const uint32_t bRowOff = (uint32_t)(wn * 32 + ((lane >> 4) & 1) * 8 + (lane & 7)) * ROWSTRIDE_B;
    const uint32_t bKsel = ((lane >> 3) & 1) * 16;

    float acc[2][4][4];
    #pragma unroll
    for (int i = 0; i < 2; i++)
        #pragma unroll
        for (int j = 0; j < 4; j++)
            #pragma unroll
            for (int q = 0; q < 4; q++) acc[i][j][q] = 0.f;

    auto load_stage = [&](int k0, int buf) {
        uint32_t sb = sbase + buf * STAGE_BYTES;
        #pragma unroll
        for (int m = 0; m < 4; m++) {
            const __nv_bfloat16* g = gsrc[m] + k0 * KSTAGE;
            cp_async16(sb + m * MAT_BYTES + r0 * ROWSTRIDE_B + s0 * 16,
                       g + (size_t)r0 * EMB + s0 * 8);
        }
    };

    // fragment loaders (8 regs per group: A = 2 x ldm.x4 over mt, B = 2 over p)
    auto ld_a = [&](uint32_t* dst, uint32_t sb, int matOff, uint32_t kByte) {
        #pragma unroll
        for (int mt = 0; mt < 2; mt++) {
            uint32_t ao = aRowOff + (uint32_t)(mt * 16) * ROWSTRIDE_B + kByte + aKsel;
            ldm_x4(dst + mt * 4, sb + matOff + ao);
        }
    };
    auto ld_b = [&](uint32_t* dst, uint32_t sb, int matOff, uint32_t kByte) {
        #pragma unroll
        for (int p = 0; p < 2; p++) {
            uint32_t bo = bRowOff + (uint32_t)(p * 16) * ROWSTRIDE_B + kByte + bKsel;
            ldm_x4(dst + p * 4, sb + matOff + bo);
        }
    };
    auto mma_pass = [&](const uint32_t* a, const uint32_t* b) {
        #pragma unroll
        for (int mt = 0; mt < 2; mt++)
            #pragma unroll
            for (int nt = 0; nt < 4; nt++)
                mma16816(acc[mt][nt], a + mt * 4, b[nt * 2], b[nt * 2 + 1]);
    };

    #pragma unroll
    for (int s = 0; s < NSTAGES - 1; s++) {
        load_stage(s, s);
        cp_commit();
    }

    uint32_t ah[2][8], al[2][8], bh[2][8], bl[2][8];

    for (int k0 = 0; k0 < KSTEPS; k0++) {
        cp_wait<NSTAGES - 2>();
        __syncthreads();
        if (k0 + NSTAGES - 1 < KSTEPS)
            load_stage(k0 + NSTAGES - 1, (k0 + NSTAGES - 1) % NSTAGES);
        cp_commit();

        const uint32_t sb = sbase + (k0 % NSTAGES) * STAGE_BYTES;

        // chunk 0 entry loads (exposed at stage boundary)
        ld_a(ah[0], sb, 0 * MAT_BYTES, 0);
        ld_b(bh[0], sb, 2 * MAT_BYTES, 0);
        // chunk 0: prefetch al -> hh -> prefetch bl -> lh -> prefetch next ah,bh -> hl
        ld_a(al[0], sb, 1 * MAT_BYTES, 0);
        mma_pass(ah[0], bh[0]);                 // hh  (covers al load)
        ld_b(bl[0], sb, 3 * MAT_BYTES, 0);
        mma_pass(al[0], bh[0]);                 // lh  (covers bl load)
        ld_a(ah[1], sb, 0 * MAT_BYTES, 32);
        ld_b(bh[1], sb, 2 * MAT_BYTES, 32);
        mma_pass(ah[0], bl[0]);                 // hl  (covers next ah/bh loads)
        // chunk 1
        ld_a(al[1], sb, 1 * MAT_BYTES, 32);
        mma_pass(ah[1], bh[1]);                 // hh
        ld_b(bl[1], sb, 3 * MAT_BYTES, 32);
        mma_pass(al[1], bh[1]);                 // lh
        mma_pass(ah[1], bl[1]);                 // hl (boundary: no prefetch)
    }
    cp_wait<0>();

    const int mrow = mBase + wm * 32 + (lane >> 2);
    const int ncol = nBase + wn * 32 + (lane & 3) * 2;
    if (mode == 0) {
        #pragma unroll
        for (int mt = 0; mt < 2; mt++)
            #pragma unroll
            for (int nt = 0; nt < 4; nt++) {
                #pragma unroll
                for (int half = 0; half < 2; half++) {
                    float v0 = acc[mt][nt][half * 2 + 0] * scale;
                    float v1 = acc[mt][nt][half * 2 + 1] * scale;
                    __nv_bfloat16 h0 = __float2bfloat16(v0);
                    __nv_bfloat16 h1 = __float2bfloat16(v1);
                    __nv_bfloat16 l0 = __float2bfloat16(v0 - __bfloat162float(h0));
                    __nv_bfloat16 l1 = __float2bfloat16(v1 - __bfloat162float(h1));
                    size_t o = (size_t)(mrow + mt * 16 + half * 8) * EMB + (ncol + nt * 8);
                    *(uint32_t*)(Chi + o) = packbf(h0, h1);
                    *(uint32_t*)(Clo + o) = packbf(l0, l1);
                }
            }
    } else {
        float* Cp = Cf + (size_t)bz * cBatch;
        #pragma unroll
        for (int mt = 0; mt < 2; mt++) {
            #pragma unroll
            for (int half = 0; half < 2; half++) {
                float rmax = -3.4e38f;
                #pragma unroll
                for (int nt = 0; nt < 4; nt++) {
                    float2 v;
                    v.x = acc[mt][nt][half * 2 + 0] * scale;
                    v.y = acc[mt][nt][half * 2 + 1] * scale;
                    rmax = fmaxf(rmax, fmaxf(v.x, v.y));
                    *(float2*)(Cp + (size_t)(mrow + mt * 16 + half * 8) * ldC + (ncol + nt * 8)) = v;
                }
                rmax = fmaxf(rmax, __shfl_xor_sync(0xffffffffu, rmax, 1));
                rmax = fmaxf(rmax, __shfl_xor_sync(0xffffffffu, rmax, 2));
                if ((lane & 3) == 0) {
                    int grow = bz * SEQ + mrow + mt * 16 + half * 8;
                    atomicMax(&g_rowmax[grow], fenc(rmax));
                }
            }
        }
    }
}

// ---------------------------------------------------------------------------
// Single-pass softmax-weighted mean (vectorized), uses precomputed row max
// ---------------------------------------------------------------------------
__global__ __launch_bounds__(256)
void softmax_out_kernel(float* __restrict__ out) {
    const int r = blockIdx.x;
    const float4* row = (const float4*)(g_L + (size_t)r * SEQ);
    const float4* vm = (const float4*)(g_vmean + (r >> 12) * SEQ);
    const int tid = threadIdx.x;
    const float m = fdec(g_rowmax[r]);

    __shared__ float red0[256];
    __shared__ float red1[256];

    float s0 = 0.f, s1 = 0.f;
    #pragma unroll
    for (int j = tid; j < SEQ / 4; j += 256) {
        float4 l = row[j];
        float4 w = vm[j];
        float e0 = __expf(l.x - m), e1 = __expf(l.y - m);
        float e2 = __expf(l.z - m), e3 = __expf(l.w - m);
        s0 += (e0 + e1) + (e2 + e3);
        s1 += e0 * w.x + e1 * w.y + e2 * w.z + e3 * w.w;
    }
    red0[tid] = s0;
    red1[tid] = s1;
    __syncthreads();
    for (int s = 128; s > 0; s >>= 1) {
        if (tid < s) { red0[tid] += red0[tid + s]; red1[tid] += red1[tid + s]; }
        __syncthreads();
    }
    if (tid == 0) out[r] = red1[0] / red0[0];
}

// ---------------------------------------------------------------------------
extern "C" void kernel_launch(void* const* d_in, const int* in_sizes, int n_in,
                              void* d_out, int out_size) {
    const float* X  = (const float*)d_in[0];
    const float* Wq = (const float*)d_in[1];
    const float* Wk = (const float*)d_in[2];
    const float* Wv = (const float*)d_in[3];
    float* out = (float*)d_out;

    __nv_bfloat16 *Xhi, *Xlo, *Wqh, *Wql, *Wkh, *Wkl, *Mth, *Mtl, *Yh, *Yl;
    float *Lp;
    cudaGetSymbolAddress((void**)&Xhi, g_Xhi);
    cudaGetSymbolAddress((void**)&Xlo, g_Xlo);
    cudaGetSymbolAddress((void**)&Wqh, g_Wq_hi);
    cudaGetSymbolAddress((void**)&Wql, g_Wq_lo);
    cudaGetSymbolAddress((void**)&Wkh, g_Wk_hi);
    cudaGetSymbolAddress((void**)&Wkl, g_Wk_lo);
    cudaGetSymbolAddress((void**)&Mth, g_Mt_hi);
    cudaGetSymbolAddress((void**)&Mtl, g_Mt_lo);
    cudaGetSymbolAddress((void**)&Yh, g_Yhi);
    cudaGetSymbolAddress((void**)&Yl, g_Ylo);
    cudaGetSymbolAddress((void**)&Lp, g_L);

    cudaFuncSetAttribute(gemm_nt_mma, cudaFuncAttributeMaxDynamicSharedMemorySize, DSMEM_BYTES);

    // 1. prep
    prep1_kernel<<<P_RM_END, 256>>>(X, Wq, Wk, Wv);
    // 2. vmean
    vmean_kernel<<<ROWS / 8, 256>>>(X);

    // 3. Mt = (Wk . Wq^T) / 32  -> split bf16   [1024 x 1024]
    {
        dim3 grid(EMB / CTN, EMB / CTM, 1);
        gemm_nt_mma<<<grid, NTHREADS, DSMEM_BYTES>>>(Wkh, Wkl, Wqh, Wql, 0, 0,
                                                     0, nullptr, 0, 0, SCALE, Mth, Mtl);
    }

    // 4. Y = X . Mt^T -> split bf16   [16384 x 1024]
    {
        dim3 grid(EMB / CTN, ROWS / CTM, 1);
        gemm_nt_mma<<<grid, NTHREADS, DSMEM_BYTES>>>(Xhi, Xlo, Mth, Mtl, 0, 0,
                                                     0, nullptr, 0, 0, 1.0f, Yh, Yl);
    }

    // 5. logits = Y . X^T (batched) + fused row-max
    {
        dim3 grid(SEQ / CTN, SEQ / CTM, BATCH);
        gemm_nt_mma<<<grid, NTHREADS, DSMEM_BYTES>>>(Yh, Yl, Xhi, Xlo,
                                                     (size_t)SEQ * EMB, (size_t)SEQ * EMB,
                                                     1, Lp, (size_t)SEQ * SEQ, SEQ, 1.0f,
                                                     nullptr, nullptr);
    }

    // 6. single-pass softmax-weighted mean
    softmax_out_kernel<<<ROWS, 256>>>(out);
}

// round 13
// speedup vs baseline: 1.1190x; 1.1189x over previous
#include <cuda_runtime.h>
#include <cuda_bf16.h>
#include <cstdint>

#define BATCH 4
#define SEQ   4096
#define EMB   1024
#define ROWS  (BATCH * SEQ)      // 16384
#define SCALE 0.03125f           // 1/sqrt(1024)

// GEMM tiling: CTA 128x128, 256 threads (2x4 warps, warp tile 64x32),
// 2-stage cp.async double buffer, 2 CTAs per SM.
#define CTM 128
#define CTN 128
#define KSTAGE 32
#define NSTAGES 2
#define KSTEPS (EMB / KSTAGE)    // 32
#define NTHREADS 256

#define ROWSTRIDE_B 80           // bytes (32 bf16 + pad)
#define MAT_BYTES  (128 * ROWSTRIDE_B)       // 10240
#define STAGE_BYTES (4 * MAT_BYTES)          // 40960
#define DSMEM_BYTES (NSTAGES * STAGE_BYTES)  // 81920 per CTA -> 2 CTAs = 160KB/SM

// ---------------------------------------------------------------------------
// Scratch (device globals)
// ---------------------------------------------------------------------------
__device__ __nv_bfloat16 g_Xhi[(size_t)ROWS * EMB];
__device__ __nv_bfloat16 g_Xlo[(size_t)ROWS * EMB];
__device__ __nv_bfloat16 g_Wq_hi[EMB * EMB], g_Wq_lo[EMB * EMB];
__device__ __nv_bfloat16 g_Wk_hi[EMB * EMB], g_Wk_lo[EMB * EMB];
__device__ __nv_bfloat16 g_Mt_hi[EMB * EMB], g_Mt_lo[EMB * EMB];   // (Wk Wq^T)/32
__device__ __nv_bfloat16 g_Yhi[(size_t)ROWS * EMB], g_Ylo[(size_t)ROWS * EMB];
__device__ float g_L[(size_t)BATCH * SEQ * SEQ];   // 256 MB
__device__ float g_vmean[ROWS];
__device__ float g_wvbar[EMB];
__device__ unsigned int g_rowmax[ROWS];

// ---------------------------------------------------------------------------
// Helpers
// ---------------------------------------------------------------------------
__device__ __forceinline__ uint32_t smem_u32(const void* p) {
    uint32_t a;
    asm("{ .reg .u64 t; cvta.to.shared.u64 t, %1; cvt.u32.u64 %0, t; }" : "=r"(a) : "l"(p));
    return a;
}
__device__ __forceinline__ void cp_async16(uint32_t dst, const void* src) {
    asm volatile("cp.async.cg.shared.global [%0], [%1], 16;" :: "r"(dst), "l"(src) : "memory");
}
__device__ __forceinline__ void cp_commit() {
    asm volatile("cp.async.commit_group;" ::: "memory");
}
template <int NN>
__device__ __forceinline__ void cp_wait() {
    asm volatile("cp.async.wait_group %0;" :: "n"(NN) : "memory");
}
__device__ __forceinline__ void ldm_x4(uint32_t* r, uint32_t addr) {
    asm volatile("ldmatrix.sync.aligned.m8n8.x4.shared.b16 {%0,%1,%2,%3}, [%4];"
                 : "=r"(r[0]), "=r"(r[1]), "=r"(r[2]), "=r"(r[3]) : "r"(addr));
}
__device__ __forceinline__ void mma16816(float* c, const uint32_t* a, uint32_t b0, uint32_t b1) {
    asm volatile("mma.sync.aligned.m16n8k16.row.col.f32.bf16.bf16.f32 "
                 "{%0,%1,%2,%3}, {%4,%5,%6,%7}, {%8,%9}, {%0,%1,%2,%3};"
                 : "+f"(c[0]), "+f"(c[1]), "+f"(c[2]), "+f"(c[3])
                 : "r"(a[0]), "r"(a[1]), "r"(a[2]), "r"(a[3]), "r"(b0), "r"(b1));
}
__device__ __forceinline__ uint32_t packbf(__nv_bfloat16 a, __nv_bfloat16 b) {
    __nv_bfloat162 t = __halves2bfloat162(a, b);
    return *reinterpret_cast<uint32_t*>(&t);
}
__device__ __forceinline__ unsigned int fenc(float f) {
    unsigned int b = __float_as_uint(f);
    return (b & 0x80000000u) ? ~b : (b | 0x80000000u);
}
__device__ __forceinline__ float fdec(unsigned int u) {
    unsigned int b = (u & 0x80000000u) ? (u & 0x7FFFFFFFu) : ~u;
    return __uint_as_float(b);
}

// ---------------------------------------------------------------------------
// prep1: range-branched mega-kernel
// ---------------------------------------------------------------------------
#define P_SPLIT_END 16384
#define P_WQ_END    17408
#define P_WK_END    18432
#define P_WV_END    18560
#define P_RM_END    18624

__device__ __forceinline__ void split4(const float4* __restrict__ src,
                                       uint2* __restrict__ hi, uint2* __restrict__ lo, int i) {
    float4 v = src[i];
    __nv_bfloat16 h0 = __float2bfloat16(v.x), h1 = __float2bfloat16(v.y);
    __nv_bfloat16 h2 = __float2bfloat16(v.z), h3 = __float2bfloat16(v.w);
    __nv_bfloat16 l0 = __float2bfloat16(v.x - __bfloat162float(h0));
    __nv_bfloat16 l1 = __float2bfloat16(v.y - __bfloat162float(h1));
    __nv_bfloat16 l2 = __float2bfloat16(v.z - __bfloat162float(h2));
    __nv_bfloat16 l3 = __float2bfloat16(v.w - __bfloat162float(h3));
    hi[i] = make_uint2(packbf(h0, h1), packbf(h2, h3));
    lo[i] = make_uint2(packbf(l0, l1), packbf(l2, l3));
}

__global__ __launch_bounds__(256)
void prep1_kernel(const float* __restrict__ X,
                  const float* __restrict__ Wq,
                  const float* __restrict__ Wk,
                  const float* __restrict__ Wv) {
    const int b = blockIdx.x;
    if (b < P_SPLIT_END) {
        split4((const float4*)X, (uint2*)g_Xhi, (uint2*)g_Xlo, b * 256 + threadIdx.x);
    } else if (b < P_WQ_END) {
        split4((const float4*)Wq, (uint2*)g_Wq_hi, (uint2*)g_Wq_lo,
               (b - P_SPLIT_END) * 256 + threadIdx.x);
    } else if (b < P_WK_END) {
        split4((const float4*)Wk, (uint2*)g_Wk_hi, (uint2*)g_Wk_lo,
               (b - P_WQ_END) * 256 + threadIdx.x);
    } else if (b < P_WV_END) {
        int row = (b - P_WK_END) * 8 + (threadIdx.x >> 5);
        int lane = threadIdx.x & 31;
        const float* p = Wv + (size_t)row * EMB;
        float s = 0.f;
        #pragma unroll 4
        for (int j = lane; j < EMB; j += 32) s += p[j];
        #pragma unroll
        for (int o = 16; o > 0; o >>= 1) s += __shfl_xor_sync(0xffffffffu, s, o);
        if (lane == 0) g_wvbar[row] = s * (1.0f / (float)EMB);
    } else {
        int i = (b - P_WV_END) * 256 + threadIdx.x;
        g_rowmax[i] = 0u;
    }
}

__global__ void vmean_kernel(const float* __restrict__ X) {
    int row = blockIdx.x * (blockDim.x >> 5) + (threadIdx.x >> 5);
    int lane = threadIdx.x & 31;
    if (row >= ROWS) return;
    const float4* p = (const float4*)(X + (size_t)row * EMB);
    const float4* w = (const float4*)g_wvbar;
    float s = 0.f;
    #pragma unroll 8
    for (int j = lane; j < EMB / 4; j += 32) {
        float4 a = p[j], b = w[j];
        s += a.x * b.x + a.y * b.y + a.z * b.z + a.w * b.w;
    }
    #pragma unroll
    for (int o = 16; o > 0; o >>= 1) s += __shfl_xor_sync(0xffffffffu, s, o);
    if (lane == 0) g_vmean[row] = s;
}

// ---------------------------------------------------------------------------
// bf16x2-split NT GEMM: 256 threads, 2x4 warps, warp tile 64x32,
// 2-stage double buffer, 2 CTAs/SM (independent barrier domains).
// C[M,N] = scale * A[M,K] . B[N,K]^T
// mode 0: write C as split bf16 (scaled); mode 1: write fp32 (scaled) + rowmax
// ---------------------------------------------------------------------------
__global__ __launch_bounds__(NTHREADS, 2)
void gemm_nt_mma(const __nv_bfloat16* __restrict__ Ahi, const __nv_bfloat16* __restrict__ Alo,
                 const __nv_bfloat16* __restrict__ Bhi, const __nv_bfloat16* __restrict__ Blo,
                 size_t aBatch, size_t bBatch, int mode,
                 float* __restrict__ Cf, size_t cBatch, int ldC, float scale,
                 __nv_bfloat16* __restrict__ Chi, __nv_bfloat16* __restrict__ Clo) {
    extern __shared__ char smem[];
    const uint32_t sbase = smem_u32(smem);
    const int tid = threadIdx.x;
    const int lane = tid & 31;
    const int wid = tid >> 5;
    const int wm = wid >> 2;          // 0..1  -> 64 rows each
    const int wn = wid & 3;           // 0..3  -> 32 cols each
    const int bz = blockIdx.z;
    const int mBase = blockIdx.y * CTM;
    const int nBase = blockIdx.x * CTN;

    const __nv_bfloat16* gsrc[4];
    gsrc[0] = Ahi + (size_t)bz * aBatch + (size_t)mBase * EMB;
    gsrc[1] = Alo + (size_t)bz * aBatch + (size_t)mBase * EMB;
    gsrc[2] = Bhi + (size_t)bz * bBatch + (size_t)nBase * EMB;
    gsrc[3] = Blo + (size_t)bz * bBatch + (size_t)nBase * EMB;

    // cp.async: 2 chunks per matrix per thread (512 chunks = 128 rows x 4)
    const int r0 = tid >> 2, s0 = tid & 3;
    const int r1 = 64 + (tid >> 2);

    const uint32_t aRowOff = (uint32_t)(wm * 64 + (lane & 15)) * ROWSTRIDE_B;
    const uint32_t aKsel = ((lane >> 4) & 1) * 16;
    const uint32_t bRowOff = (uint32_t)(wn * 32 + ((lane >> 4) & 1) * 8 + (lane & 7)) * ROWSTRIDE_B;
    const uint32_t bKsel = ((lane >> 3) & 1) * 16;

    float acc[4][4][4];
    #pragma unroll
    for (int i = 0; i < 4; i++)
        #pragma unroll
        for (int j = 0; j < 4; j++)
            #pragma unroll
            for (int q = 0; q < 4; q++) acc[i][j][q] = 0.f;

    auto load_stage = [&](int k0, int buf) {
        uint32_t sb = sbase + buf * STAGE_BYTES;
        #pragma unroll
        for (int m = 0; m < 4; m++) {
            const __nv_bfloat16* g = gsrc[m] + k0 * KSTAGE;
            cp_async16(sb + m * MAT_BYTES + r0 * ROWSTRIDE_B + s0 * 16,
                       g + (size_t)r0 * EMB + s0 * 8);
            cp_async16(sb + m * MAT_BYTES + r1 * ROWSTRIDE_B + s0 * 16,
                       g + (size_t)r1 * EMB + s0 * 8);
        }
    };

    // prologue: fill stage 0
    load_stage(0, 0);
    cp_commit();

    for (int k0 = 0; k0 < KSTEPS; k0++) {
        cp_wait<0>();
        __syncthreads();
        if (k0 + 1 < KSTEPS)
            load_stage(k0 + 1, (k0 + 1) & 1);
        cp_commit();

        const uint32_t sb = sbase + (k0 & 1) * STAGE_BYTES;
        #pragma unroll
        for (int kk = 0; kk < 2; kk++) {
            const uint32_t kByte = kk * 32;
            uint32_t ah[4][4], al[4][4], bh[8], bl[8];
            #pragma unroll
            for (int mt = 0; mt < 4; mt++) {
                uint32_t ao = aRowOff + (uint32_t)(mt * 16) * ROWSTRIDE_B + kByte + aKsel;
                ldm_x4(ah[mt], sb + 0 * MAT_BYTES + ao);
                ldm_x4(al[mt], sb + 1 * MAT_BYTES + ao);
            }
            #pragma unroll
            for (int p = 0; p < 2; p++) {
                uint32_t bo = bRowOff + (uint32_t)(p * 16) * ROWSTRIDE_B + kByte + bKsel;
                ldm_x4(&bh[p * 4], sb + 2 * MAT_BYTES + bo);
                ldm_x4(&bl[p * 4], sb + 3 * MAT_BYTES + bo);
            }
            // pass-major: independent accumulators within each pass
            #pragma unroll
            for (int mt = 0; mt < 4; mt++)
                #pragma unroll
                for (int nt = 0; nt < 4; nt++)
                    mma16816(acc[mt][nt], ah[mt], bh[nt * 2], bh[nt * 2 + 1]);
            #pragma unroll
            for (int mt = 0; mt < 4; mt++)
                #pragma unroll
                for (int nt = 0; nt < 4; nt++)
                    mma16816(acc[mt][nt], ah[mt], bl[nt * 2], bl[nt * 2 + 1]);
            #pragma unroll
            for (int mt = 0; mt < 4; mt++)
                #pragma unroll
                for (int nt = 0; nt < 4; nt++)
                    mma16816(acc[mt][nt], al[mt], bh[nt * 2], bh[nt * 2 + 1]);
        }
    }
    cp_wait<0>();

    const int mrow = mBase + wm * 64 + (lane >> 2);
    const int ncol = nBase + wn * 32 + (lane & 3) * 2;
    if (mode == 0) {
        #pragma unroll
        for (int mt = 0; mt < 4; mt++)
            #pragma unroll
            for (int nt = 0; nt < 4; nt++) {
                #pragma unroll
                for (int half = 0; half < 2; half++) {
                    float v0 = acc[mt][nt][half * 2 + 0] * scale;
                    float v1 = acc[mt][nt][half * 2 + 1] * scale;
                    __nv_bfloat16 h0 = __float2bfloat16(v0);
                    __nv_bfloat16 h1 = __float2bfloat16(v1);
                    __nv_bfloat16 l0 = __float2bfloat16(v0 - __bfloat162float(h0));
                    __nv_bfloat16 l1 = __float2bfloat16(v1 - __bfloat162float(h1));
                    size_t o = (size_t)(mrow + mt * 16 + half * 8) * EMB + (ncol + nt * 8);
                    *(uint32_t*)(Chi + o) = packbf(h0, h1);
                    *(uint32_t*)(Clo + o) = packbf(l0, l1);
                }
            }
    } else {
        float* Cp = Cf + (size_t)bz * cBatch;
        #pragma unroll
        for (int mt = 0; mt < 4; mt++) {
            #pragma unroll
            for (int half = 0; half < 2; half++) {
                float rmax = -3.4e38f;
                #pragma unroll
                for (int nt = 0; nt < 4; nt++) {
                    float2 v;
                    v.x = acc[mt][nt][half * 2 + 0] * scale;
                    v.y = acc[mt][nt][half * 2 + 1] * scale;
                    rmax = fmaxf(rmax, fmaxf(v.x, v.y));
                    *(float2*)(Cp + (size_t)(mrow + mt * 16 + half * 8) * ldC + (ncol + nt * 8)) = v;
                }
                rmax = fmaxf(rmax, __shfl_xor_sync(0xffffffffu, rmax, 1));
                rmax = fmaxf(rmax, __shfl_xor_sync(0xffffffffu, rmax, 2));
                if ((lane & 3) == 0) {
                    int grow = bz * SEQ + mrow + mt * 16 + half * 8;
                    atomicMax(&g_rowmax[grow], fenc(rmax));
                }
            }
        }
    }
}

// ---------------------------------------------------------------------------
// Single-pass softmax-weighted mean (vectorized), uses precomputed row max
// ---------------------------------------------------------------------------
__global__ __launch_bounds__(256)
void softmax_out_kernel(float* __restrict__ out) {
    const int r = blockIdx.x;
    const float4* row = (const float4*)(g_L + (size_t)r * SEQ);
    const float4* vm = (const float4*)(g_vmean + (r >> 12) * SEQ);
    const int tid = threadIdx.x;
    const float m = fdec(g_rowmax[r]);

    __shared__ float red0[256];
    __shared__ float red1[256];

    float s0 = 0.f, s1 = 0.f;
    #pragma unroll
    for (int j = tid; j < SEQ / 4; j += 256) {
        float4 l = row[j];
        float4 w = vm[j];
        float e0 = __expf(l.x - m), e1 = __expf(l.y - m);
        float e2 = __expf(l.z - m), e3 = __expf(l.w - m);
        s0 += (e0 + e1) + (e2 + e3);
        s1 += e0 * w.x + e1 * w.y + e2 * w.z + e3 * w.w;
    }
    red0[tid] = s0;
    red1[tid] = s1;
    __syncthreads();
    for (int s = 128; s > 0; s >>= 1) {
        if (tid < s) { red0[tid] += red0[tid + s]; red1[tid] += red1[tid + s]; }
        __syncthreads();
    }
    if (tid == 0) out[r] = red1[0] / red0[0];
}

// ---------------------------------------------------------------------------
extern "C" void kernel_launch(void* const* d_in, const int* in_sizes, int n_in,
                              void* d_out, int out_size) {
    const float* X  = (const float*)d_in[0];
    const float* Wq = (const float*)d_in[1];
    const float* Wk = (const float*)d_in[2];
    const float* Wv = (const float*)d_in[3];
    float* out = (float*)d_out;

    __nv_bfloat16 *Xhi, *Xlo, *Wqh, *Wql, *Wkh, *Wkl, *Mth, *Mtl, *Yh, *Yl;
    float *Lp;
    cudaGetSymbolAddress((void**)&Xhi, g_Xhi);
    cudaGetSymbolAddress((void**)&Xlo, g_Xlo);
    cudaGetSymbolAddress((void**)&Wqh, g_Wq_hi);
    cudaGetSymbolAddress((void**)&Wql, g_Wq_lo);
    cudaGetSymbolAddress((void**)&Wkh, g_Wk_hi);
    cudaGetSymbolAddress((void**)&Wkl, g_Wk_lo);
    cudaGetSymbolAddress((void**)&Mth, g_Mt_hi);
    cudaGetSymbolAddress((void**)&Mtl, g_Mt_lo);
    cudaGetSymbolAddress((void**)&Yh, g_Yhi);
    cudaGetSymbolAddress((void**)&Yl, g_Ylo);
    cudaGetSymbolAddress((void**)&Lp, g_L);

    cudaFuncSetAttribute(gemm_nt_mma, cudaFuncAttributeMaxDynamicSharedMemorySize, DSMEM_BYTES);

    // 1. prep
    prep1_kernel<<<P_RM_END, 256>>>(X, Wq, Wk, Wv);
    // 2. vmean
    vmean_kernel<<<ROWS / 8, 256>>>(X);

    // 3. Mt = (Wk . Wq^T) / 32  -> split bf16   [1024 x 1024]
    {
        dim3 grid(EMB / CTN, EMB / CTM, 1);
        gemm_nt_mma<<<grid, NTHREADS, DSMEM_BYTES>>>(Wkh, Wkl, Wqh, Wql, 0, 0,
                                                     0, nullptr, 0, 0, SCALE, Mth, Mtl);
    }

    // 4. Y = X . Mt^T -> split bf16   [16384 x 1024]
    {
        dim3 grid(EMB / CTN, ROWS / CTM, 1);
        gemm_nt_mma<<<grid, NTHREADS, DSMEM_BYTES>>>(Xhi, Xlo, Mth, Mtl, 0, 0,
                                                     0, nullptr, 0, 0, 1.0f, Yh, Yl);
    }

    // 5. logits = Y . X^T (batched) + fused row-max
    {
        dim3 grid(SEQ / CTN, SEQ / CTM, BATCH);
        gemm_nt_mma<<<grid, NTHREADS, DSMEM_BYTES>>>(Yh, Yl, Xhi, Xlo,
                                                     (size_t)SEQ * EMB, (size_t)SEQ * EMB,
                                                     1, Lp, (size_t)SEQ * SEQ, SEQ, 1.0f,
                                                     nullptr, nullptr);
    }

    // 6. single-pass softmax-weighted mean
    softmax_out_kernel<<<ROWS, 256>>>(out);
}